// round 16
// baseline (speedup 1.0000x reference)
#include <cuda_runtime.h>
#include <cstdint>

// Problem: B=32, C=8, H=256, W=256 -> 256 maps of 65536 floats, 2 tensors.
#define NMAPS    256
#define NBLK     1024         // 4 quarter-map CTAs per map; 148*7=1036 -> single balanced wave
#define NTHR     256
#define QUART_F4 4096         // float4s per quarter-map per tensor
#define CHUNK_F4 256          // 1 float4 per thread per tensor per chunk (4 KB)
#define NCHUNK   16
#define NSTAGES  3            // 2 x 12 KB stages = 24 KB -> 7 CTAs/SM

// Per-quarter partials (no allocation: __device__ globals).
__device__ float        g_s [NBLK];
__device__ float        g_sx[NBLK];
__device__ float        g_sy[NBLK];
__device__ float        g_m [NBLK];
__device__ int          g_i [NBLK];
__device__ unsigned int g_count = 0;

// cp.async with an L2 cache policy.
__device__ __forceinline__ void cp16p(float4* dst_smem, const float4* src,
                                      unsigned long long pol) {
    uint32_t d = (uint32_t)__cvta_generic_to_shared(dst_smem);
    asm volatile("cp.async.cg.shared.global.L2::cache_hint [%0], [%1], 16, %2;\n"
                 :: "r"(d), "l"(src), "l"(pol));
}

__global__ __launch_bounds__(NTHR, 7)
void dsnt_bal_l2_kernel(const float* __restrict__ inp,
                        const float* __restrict__ tgt,
                        float* __restrict__ out) {
    __shared__ float4 smi[NSTAGES][CHUNK_F4];   // input stages,  12 KB
    __shared__ float4 smt[NSTAGES][CHUNK_F4];   // target stages, 12 KB
    __shared__ float  sh_s [8], sh_sx[8], sh_sy[8], sh_m [8], sh_ed[8];
    __shared__ int    sh_i [8], sh_fl[1];

    const int blk = blockIdx.x;
    const int tid = threadIdx.x;
    const float4* __restrict__ in4 = (const float4*)inp + (size_t)blk * QUART_F4;
    const float4* __restrict__ tg4 = (const float4*)tgt + (size_t)blk * QUART_F4;
    const int ebase = (blk & 3) << 14;          // element offset within the map

    // L2 policies: input fully persistent; target 40% persistent (R13/R14-validated).
    unsigned long long pol_keep, pol_tgt;
    asm volatile("createpolicy.fractional.L2::evict_last.b64 %0, 1.0;" : "=l"(pol_keep));
    asm volatile("createpolicy.fractional.L2::evict_last.L2::evict_first.b64 %0, 0.40;"
                 : "=l"(pol_tgt));

    // ---- thread-private 3-stage pipeline: thread owns slot tid of each chunk.
    // Target copies first in each group (they pace completion).
    #pragma unroll
    for (int k = 0; k < NSTAGES - 1; ++k) {
        cp16p(&smt[k][tid], tg4 + k * CHUNK_F4 + tid, pol_tgt);
        cp16p(&smi[k][tid], in4 + k * CHUNK_F4 + tid, pol_keep);
        asm volatile("cp.async.commit_group;\n" ::: "memory");
    }

    float s = 0.f, sx = 0.f, sy = 0.f;
    float tmax = -1e30f;
    int   jbest = 0;                            // winning f4 index (local)

    #pragma unroll
    for (int k = 0; k < NCHUNK; ++k) {
        const int slot = k % NSTAGES;
        asm volatile("cp.async.wait_group %0;\n" :: "n"(NSTAGES - 2) : "memory");

        float4 a = smi[slot][tid];
        float4 t = smt[slot][tid];

        // refill this thread's slots for chunk k+2 (thread-private, no barrier)
        const int kn = k + NSTAGES - 1;
        if (kn < NCHUNK) {
            const int sl = kn % NSTAGES;
            cp16p(&smt[sl][tid], tg4 + kn * CHUNK_F4 + tid, pol_tgt);
            cp16p(&smi[sl][tid], in4 + kn * CHUNK_F4 + tid, pol_keep);
        }
        asm volatile("cp.async.commit_group;\n" ::: "memory");

        // ---- accumulate ----
        int j   = k * CHUNK_F4 + tid;           // local f4 index
        int e0  = ebase + (j << 2);
        int col = e0 & 255;
        int row = e0 >> 8;
        float ex = __expf(a.x);
        float ey = __expf(a.y);
        float ez = __expf(a.z);
        float ew = __expf(a.w);
        float es = (ex + ey) + (ez + ew);
        s  += es;
        sy  = fmaf(es, (float)(row + 1), sy);
        float extra = fmaf(2.f, ez, ey);
        extra = fmaf(3.f, ew, extra);
        sx += fmaf(es, (float)(col + 1), extra);
        // tree max; strict > with ascending j keeps earliest winning f4
        float v = fmaxf(fmaxf(t.x, t.y), fmaxf(t.z, t.w));
        if (v > tmax) { tmax = v; jbest = j; }
    }

    // reload the winning float4 (L2 hit) to find the within-f4 index; first match
    // = lowest element index, consistent with the ascending scan tie-break.
    float4 wt = __ldg(tg4 + jbest);
    int c = (wt.x == tmax) ? 0 : (wt.y == tmax) ? 1 : (wt.z == tmax) ? 2 : 3;
    int tidx = ebase + (jbest << 2) + c;

    // ---- warp reduction ----
    const unsigned FULL = 0xFFFFFFFFu;
    #pragma unroll
    for (int o = 16; o > 0; o >>= 1) {
        s  += __shfl_down_sync(FULL, s,  o);
        sx += __shfl_down_sync(FULL, sx, o);
        sy += __shfl_down_sync(FULL, sy, o);
        float om = __shfl_down_sync(FULL, tmax, o);
        int   oi = __shfl_down_sync(FULL, tidx, o);
        if (om > tmax || (om == tmax && oi < tidx)) { tmax = om; tidx = oi; }
    }

    // ---- cross-warp reduction (8 warps) ----
    const int lane = tid & 31;
    const int wid  = tid >> 5;
    if (lane == 0) {
        sh_s [wid] = s;  sh_sx[wid] = sx;  sh_sy[wid] = sy;
        sh_m [wid] = tmax;  sh_i [wid] = tidx;
    }
    __syncthreads();

    if (wid == 0) {
        s    = (lane < 8) ? sh_s [lane] : 0.f;
        sx   = (lane < 8) ? sh_sx[lane] : 0.f;
        sy   = (lane < 8) ? sh_sy[lane] : 0.f;
        tmax = (lane < 8) ? sh_m [lane] : -1e30f;
        tidx = (lane < 8) ? sh_i [lane] : 0x7FFFFFFF;
        #pragma unroll
        for (int o = 4; o > 0; o >>= 1) {
            s  += __shfl_down_sync(FULL, s,  o);
            sx += __shfl_down_sync(FULL, sx, o);
            sy += __shfl_down_sync(FULL, sy, o);
            float om = __shfl_down_sync(FULL, tmax, o);
            int   oi = __shfl_down_sync(FULL, tidx, o);
            if (om > tmax || (om == tmax && oi < tidx)) { tmax = om; tidx = oi; }
        }
        if (lane == 0) {
            g_s [blk] = s;  g_sx[blk] = sx;  g_sy[blk] = sy;
            g_m [blk] = tmax;  g_i [blk] = tidx;
            __threadfence();
            unsigned int prev = atomicAdd(&g_count, 1u);
            sh_fl[0] = (prev == NBLK - 1) ? 1 : 0;
        }
    }
    __syncthreads();

    // ---- last CTA: fold 1024 quarter partials -> 256 maps -> scalar ----
    if (sh_fl[0]) {
        __threadfence();                       // acquire all partials
        const int m = tid;                     // map index 0..255
        float S = 0.f, SX = 0.f, SY = 0.f;
        float M = -1e30f;
        int   I = 0x7FFFFFFF;
        #pragma unroll
        for (int q = 0; q < 4; ++q) {          // ascending quarters: strict > keeps lowest index
            int b = 4 * m + q;
            S  += g_s [b];
            SX += g_sx[b];
            SY += g_sy[b];
            float om = g_m[b];
            if (om > M) { M = om; I = g_i[b]; }
        }
        float inv = 1.0f / (S * 256.0f);
        float px = SX * inv;
        float py = SY * inv;
        float tx = (float)((I & 255) + 1) * (1.0f / 256.0f);
        float ty = (float)((I >> 8)  + 1) * (1.0f / 256.0f);
        float dx = tx - px, dy = ty - py;
        float ed = sqrtf(dx * dx + dy * dy);

        #pragma unroll
        for (int o = 16; o > 0; o >>= 1) ed += __shfl_down_sync(FULL, ed, o);
        if (lane == 0) sh_ed[wid] = ed;
        __syncthreads();
        if (wid == 0) {
            ed = (lane < 8) ? sh_ed[lane] : 0.f;
            #pragma unroll
            for (int o = 4; o > 0; o >>= 1) ed += __shfl_down_sync(FULL, ed, o);
            if (lane == 0) {
                out[0] = ed * (1.0f / 32.0f);
                g_count = 0;                   // reset for next graph replay
            }
        }
    }
}

extern "C" void kernel_launch(void* const* d_in, const int* in_sizes, int n_in,
                              void* d_out, int out_size) {
    const float* inp = (const float*)d_in[0];
    const float* tgt = (const float*)d_in[1];
    dsnt_bal_l2_kernel<<<NBLK, NTHR>>>(inp, tgt, (float*)d_out);
}

// round 17
// speedup vs baseline: 1.2183x; 1.2183x over previous
#include <cuda_runtime.h>
#include <cstdint>

// Problem: B=32, C=8, H=256, W=256 -> 256 maps of 65536 floats, 2 tensors.
#define NMAPS    256
#define NBLK     512          // 2 half-map CTAs per map (winning shape)
#define NTHR     256
#define HALF_F4  8192         // float4s per half-map per tensor
#define CHUNK_F4 256          // 1 float4 per thread per tensor per chunk (4 KB)
#define NCHUNK   32           // chunks per half-map
#define NSTAGES  6            // 6 x 8 KB = 48 KB stage smem (same as R14) -> 4 CTAs/SM

// Per-half-map partials (no allocation: __device__ globals).
__device__ float        g_s [NBLK];
__device__ float        g_sx[NBLK];
__device__ float        g_sy[NBLK];
__device__ float        g_m [NBLK];
__device__ int          g_i [NBLK];
__device__ unsigned int g_count = 0;

// cp.async with an L2 cache policy.
__device__ __forceinline__ void cp16p(float4* dst_smem, const float4* src,
                                      unsigned long long pol) {
    uint32_t d = (uint32_t)__cvta_generic_to_shared(dst_smem);
    asm volatile("cp.async.cg.shared.global.L2::cache_hint [%0], [%1], 16, %2;\n"
                 :: "r"(d), "l"(src), "l"(pol));
}

__device__ __forceinline__ void accum4(float4 a, float4 t, int e0,
                                       float& s, float& sx, float& sy,
                                       float& tmax, int& ebest,
                                       float& wx, float& wy, float& wz, float& ww) {
    int col = e0 & 255;
    int row = e0 >> 8;
    float ex = __expf(a.x);
    float ey = __expf(a.y);
    float ez = __expf(a.z);
    float ew = __expf(a.w);
    float es = (ex + ey) + (ez + ew);
    s  += es;
    sy  = fmaf(es, (float)(row + 1), sy);
    float extra = fmaf(2.f, ez, ey);
    extra = fmaf(3.f, ew, extra);
    sx += fmaf(es, (float)(col + 1), extra);
    // tree max + single conditional keep; strict > + ascending e0 = first index
    float v = fmaxf(fmaxf(t.x, t.y), fmaxf(t.z, t.w));
    if (v > tmax) { tmax = v; ebest = e0; wx = t.x; wy = t.y; wz = t.z; ww = t.w; }
}

__global__ __launch_bounds__(NTHR)
void dsnt_pipe6_kernel(const float* __restrict__ inp,
                       const float* __restrict__ tgt,
                       float* __restrict__ out) {
    __shared__ float4 smi[NSTAGES][CHUNK_F4];   // input stages,  24 KB
    __shared__ float4 smt[NSTAGES][CHUNK_F4];   // target stages, 24 KB
    __shared__ float  sh_s [8], sh_sx[8], sh_sy[8], sh_m [8], sh_ed[8];
    __shared__ int    sh_i [8], sh_fl[1];

    const int blk = blockIdx.x;
    const int tid = threadIdx.x;
    const float4* __restrict__ in4 = (const float4*)inp + (size_t)blk * HALF_F4;
    const float4* __restrict__ tg4 = (const float4*)tgt + (size_t)blk * HALF_F4;
    const int ebase = (blk & 1) << 15;          // element offset within the map

    // L2 policies: input fully persistent; target 40% persistent (validated).
    unsigned long long pol_keep, pol_tgt;
    asm volatile("createpolicy.fractional.L2::evict_last.b64 %0, 1.0;" : "=l"(pol_keep));
    asm volatile("createpolicy.fractional.L2::evict_last.L2::evict_first.b64 %0, 0.40;"
                 : "=l"(pol_tgt));

    // ---- thread-private 6-stage pipeline: thread owns slot tid of each chunk.
    // Target copy first in each group (it paces completion from DRAM).
    #pragma unroll
    for (int k = 0; k < NSTAGES - 1; ++k) {
        cp16p(&smt[k][tid], tg4 + k * CHUNK_F4 + tid, pol_tgt);
        cp16p(&smi[k][tid], in4 + k * CHUNK_F4 + tid, pol_keep);
        asm volatile("cp.async.commit_group;\n" ::: "memory");
    }

    float s = 0.f, sx = 0.f, sy = 0.f;
    float tmax = -1e30f;
    int   ebest = 0;
    float wx = 0.f, wy = 0.f, wz = 0.f, ww = 0.f;

    #pragma unroll
    for (int k = 0; k < NCHUNK; ++k) {
        const int slot = k % NSTAGES;
        asm volatile("cp.async.wait_group %0;\n" :: "n"(NSTAGES - 2) : "memory");

        float4 a = smi[slot][tid];
        float4 t = smt[slot][tid];

        // refill this thread's slots for chunk k+5 (thread-private, no barrier)
        const int kn = k + NSTAGES - 1;
        if (kn < NCHUNK) {
            const int sl = kn % NSTAGES;
            cp16p(&smt[sl][tid], tg4 + kn * CHUNK_F4 + tid, pol_tgt);
            cp16p(&smi[sl][tid], in4 + kn * CHUNK_F4 + tid, pol_keep);
        }
        asm volatile("cp.async.commit_group;\n" ::: "memory");

        int e0 = ebase + ((k * CHUNK_F4 + tid) << 2);
        accum4(a, t, e0, s, sx, sy, tmax, ebest, wx, wy, wz, ww);
    }

    // reconstruct element index within the winning float4 (first match wins)
    int c = (wx == tmax) ? 0 : (wy == tmax) ? 1 : (wz == tmax) ? 2 : 3;
    int tidx = ebest + c;

    // ---- warp reduction ----
    const unsigned FULL = 0xFFFFFFFFu;
    #pragma unroll
    for (int o = 16; o > 0; o >>= 1) {
        s  += __shfl_down_sync(FULL, s,  o);
        sx += __shfl_down_sync(FULL, sx, o);
        sy += __shfl_down_sync(FULL, sy, o);
        float om = __shfl_down_sync(FULL, tmax, o);
        int   oi = __shfl_down_sync(FULL, tidx, o);
        if (om > tmax || (om == tmax && oi < tidx)) { tmax = om; tidx = oi; }
    }

    // ---- cross-warp reduction (8 warps) ----
    const int lane = tid & 31;
    const int wid  = tid >> 5;
    if (lane == 0) {
        sh_s [wid] = s;  sh_sx[wid] = sx;  sh_sy[wid] = sy;
        sh_m [wid] = tmax;  sh_i [wid] = tidx;
    }
    __syncthreads();

    if (wid == 0) {
        s    = (lane < 8) ? sh_s [lane] : 0.f;
        sx   = (lane < 8) ? sh_sx[lane] : 0.f;
        sy   = (lane < 8) ? sh_sy[lane] : 0.f;
        tmax = (lane < 8) ? sh_m [lane] : -1e30f;
        tidx = (lane < 8) ? sh_i [lane] : 0x7FFFFFFF;
        #pragma unroll
        for (int o = 4; o > 0; o >>= 1) {
            s  += __shfl_down_sync(FULL, s,  o);
            sx += __shfl_down_sync(FULL, sx, o);
            sy += __shfl_down_sync(FULL, sy, o);
            float om = __shfl_down_sync(FULL, tmax, o);
            int   oi = __shfl_down_sync(FULL, tidx, o);
            if (om > tmax || (om == tmax && oi < tidx)) { tmax = om; tidx = oi; }
        }
        if (lane == 0) {
            g_s [blk] = s;  g_sx[blk] = sx;  g_sy[blk] = sy;
            g_m [blk] = tmax;  g_i [blk] = tidx;
            __threadfence();
            unsigned int prev = atomicAdd(&g_count, 1u);
            sh_fl[0] = (prev == NBLK - 1) ? 1 : 0;
        }
    }
    __syncthreads();

    // ---- last CTA: combine 512 partials -> 256 distances -> scalar ----
    if (sh_fl[0]) {
        __threadfence();                  // acquire all partials
        const int m = tid;                // map index 0..255
        float s0  = g_s [2*m],   s1  = g_s [2*m+1];
        float sx0 = g_sx[2*m],   sx1 = g_sx[2*m+1];
        float sy0 = g_sy[2*m],   sy1 = g_sy[2*m+1];
        float m0  = g_m [2*m],   m1  = g_m [2*m+1];
        int   i0  = g_i [2*m],   i1  = g_i [2*m+1];

        float S  = s0 + s1;
        float SX = sx0 + sx1;
        float SY = sy0 + sy1;
        int   I  = (m1 > m0) ? i1 : i0;   // first half has lower indices

        float inv = 1.0f / (S * 256.0f);
        float px = SX * inv;
        float py = SY * inv;
        float tx = (float)((I & 255) + 1) * (1.0f / 256.0f);
        float ty = (float)((I >> 8)  + 1) * (1.0f / 256.0f);
        float dx = tx - px, dy = ty - py;
        float ed = sqrtf(dx * dx + dy * dy);

        #pragma unroll
        for (int o = 16; o > 0; o >>= 1) ed += __shfl_down_sync(FULL, ed, o);
        if (lane == 0) sh_ed[wid] = ed;
        __syncthreads();
        if (wid == 0) {
            ed = (lane < 8) ? sh_ed[lane] : 0.f;
            #pragma unroll
            for (int o = 4; o > 0; o >>= 1) ed += __shfl_down_sync(FULL, ed, o);
            if (lane == 0) {
                out[0] = ed * (1.0f / 32.0f);
                g_count = 0;              // reset for next graph replay
            }
        }
    }
}

extern "C" void kernel_launch(void* const* d_in, const int* in_sizes, int n_in,
                              void* d_out, int out_size) {
    const float* inp = (const float*)d_in[0];
    const float* tgt = (const float*)d_in[1];
    dsnt_pipe6_kernel<<<NBLK, NTHR>>>(inp, tgt, (float*)d_out);
}